// round 10
// baseline (speedup 1.0000x reference)
#include <cuda_runtime.h>

#define N3 262144
#define N2 65536
#define N1 16384

typedef unsigned long long ull;

// ---------------- scratch (device globals; no allocations allowed) ----------
__device__ float g_x8   [N3 * 16];
__device__ float g_x7p  [N2 * 16];
__device__ float g_x7   [N2 * 32];
__device__ float g_x6p  [N1 * 32];
__device__ float g_x6   [N1 * 64];
__device__ float g_x7dec[N2 * 32];
__device__ float g_x8dec[N3 * 16];
__device__ int   g_pidx3[N3];
__device__ int   g_pidx2[N2];

// ---------------- packed f32x2 helpers ---------------------------------------
__device__ __forceinline__ ull pack2(float lo, float hi) {
    ull r;
    asm("mov.b64 %0, {%1, %2};" : "=l"(r) : "f"(lo), "f"(hi));
    return r;
}
__device__ __forceinline__ ull bcast2(float v) {
    ull r;
    asm("mov.b64 %0, {%1, %1};" : "=l"(r) : "f"(v));
    return r;
}
__device__ __forceinline__ void ffma2(ull& d, ull a, ull b) {
    asm("fma.rn.f32x2 %0, %1, %2, %0;" : "+l"(d) : "l"(a), "l"(b));
}
__device__ __forceinline__ ull add2(ull a, ull b) {
    ull r;
    asm("add.rn.f32x2 %0, %1, %2;" : "=l"(r) : "l"(a), "l"(b));
    return r;
}
__device__ __forceinline__ float2 unpack2(ull v) {
    float2 r;
    asm("mov.b64 {%0, %1}, %2;" : "=f"(r.x), "=f"(r.y) : "l"(v));
    return r;
}

// ---------------- fused prep: pidx3, pidx2, zero x7p, zero x6p ---------------
__device__ __forceinline__ int lower_bound_shift(const int* __restrict__ keys,
                                                 int Np, int v) {
    int lo = 0, hi = Np;
    while (lo < hi) {
        int mid = (lo + hi) >> 1;
        if (keys[mid] < v) lo = mid + 1; else hi = mid;
    }
    return lo;
}

__global__ void prep_kernel(const int* __restrict__ keys3,
                            const int* __restrict__ keys2,
                            const int* __restrict__ keys1,
                            int* __restrict__ pidx3, int* __restrict__ pidx2,
                            float* __restrict__ x7p, float* __restrict__ x6p) {
    const int T0 = N3;
    const int T1 = T0 + N2;
    const int T2 = T1 + N2 * 16;
    const int T3 = T2 + N1 * 32;
    int i = blockIdx.x * blockDim.x + threadIdx.x;
    int stride = gridDim.x * blockDim.x;
    for (; i < T3; i += stride) {
        if (i < T0) {
            pidx3[i] = lower_bound_shift(keys2, N2, keys3[i] >> 2);
        } else if (i < T1) {
            int k = i - T0;
            pidx2[k] = lower_bound_shift(keys1, N1, keys2[k] >> 2);
        } else if (i < T2) {
            x7p[i - T1] = 0.0f;
        } else {
            x6p[i - T2] = 0.0f;
        }
    }
}

// segment-max pool. Post-ReLU values >= 0, so int-bit atomicMax == float max
// and 0-init matches the reference's (-inf -> 0) fill.
template <int C>
__global__ void pool_kernel(const float* __restrict__ child,
                            const int* __restrict__ pidx,
                            int Nc, int Np, float* __restrict__ parent) {
    int i = blockIdx.x * blockDim.x + threadIdx.x;
    if (i >= Nc * C) return;
    int node = i / C;
    int c = i - node * C;
    int p = pidx[node];
    if (p < Np) {
        float v = child[i];
        atomicMax(reinterpret_cast<int*>(&parent[(size_t)p * C + c]),
                  __float_as_int(v));
    }
}

// ---------------- fused gather + (9*CIN -> COUT) conv -----------------------
// S = CIN-split: S consecutive lanes share one node; lane s owns float4
// channel-groups g*S+s (interleaved -> the S lanes read contiguous 16B chunks
// of the gathered row => ~S x fewer L1TEX wavefronts, S x more warps in
// flight). Packed f32x2 accumulators; shfl_xor butterfly reduces the split.
// INDIRECT fuses the unpool gather (row = clamp(pidx[idx])).
template <int CIN, int COB, int S, int NPN, bool RELU, bool INDIRECT>
__global__ void __launch_bounds__(256)
conv_kernel(const float* __restrict__ feat, const int* __restrict__ neigh,
            const int* __restrict__ pidx, int Nfeat, int ostride,
            const float* __restrict__ w, const float* __restrict__ b,
            float* __restrict__ out) {
    extern __shared__ __align__(16) char smem_raw[];
    const int tid = threadIdx.x;
    const int cin9 = 9 * CIN;

    if constexpr (COB == 1) {
        // tiny head layer: scalar path, weights in shared as float
        float* ws = reinterpret_cast<float*>(smem_raw);
        for (int s = tid; s < cin9; s += 256) ws[s] = w[s];
        __syncthreads();

        int node[NPN];
        int idx[NPN][9];
#pragma unroll
        for (int t = 0; t < NPN; t++) {
            node[t] = blockIdx.x * (256 * NPN) + t * 256 + tid;
#pragma unroll
            for (int j = 0; j < 9; j++)
                idx[t][j] = neigh[(size_t)node[t] * 9 + j];
        }
        float acc[NPN];
#pragma unroll
        for (int t = 0; t < NPN; t++) acc[t] = b[0];
        for (int j = 0; j < 9; j++) {
#pragma unroll
            for (int c4 = 0; c4 < CIN; c4 += 4) {
                float4 wv = *reinterpret_cast<const float4*>(&ws[j * CIN + c4]);
#pragma unroll
                for (int t = 0; t < NPN; t++) {
                    float4 f = (idx[t][j] >= 0)
                        ? *reinterpret_cast<const float4*>(
                              &feat[(size_t)idx[t][j] * CIN + c4])
                        : make_float4(0.f, 0.f, 0.f, 0.f);
                    acc[t] += f.x * wv.x + f.y * wv.y + f.z * wv.z + f.w * wv.w;
                }
            }
        }
#pragma unroll
        for (int t = 0; t < NPN; t++)
            out[(size_t)node[t] * ostride] = RELU ? fmaxf(acc[t], 0.f) : acc[t];
    } else {
        constexpr int PAIRS = COB / 2;
        ull* ws = reinterpret_cast<ull*>(smem_raw);
        // ws[rc * PAIRS + o2] = pack(w[2*o2][rc], w[2*o2+1][rc]), rc = j*CIN+c
        for (int sIdx = tid; sIdx < cin9 * PAIRS; sIdx += 256) {
            int rc = sIdx / PAIRS;
            int o2 = sIdx - rc * PAIRS;
            ws[sIdx] = pack2(w[(size_t)(2 * o2) * cin9 + rc],
                             w[(size_t)(2 * o2 + 1) * cin9 + rc]);
        }
        __syncthreads();

        if constexpr (S == 1) {
            // CIN==1 (enc1): packed path, NPN nodes/thread
            int node[NPN];
            int idx[NPN][9];
#pragma unroll
            for (int t = 0; t < NPN; t++) {
                node[t] = blockIdx.x * (256 * NPN) + t * 256 + tid;
#pragma unroll
                for (int j = 0; j < 9; j++)
                    idx[t][j] = neigh[(size_t)node[t] * 9 + j];
            }
            ull acc2[NPN][PAIRS];
#pragma unroll
            for (int o2 = 0; o2 < PAIRS; o2++) {
                ull bv = pack2(b[2 * o2], b[2 * o2 + 1]);
#pragma unroll
                for (int t = 0; t < NPN; t++) acc2[t][o2] = bv;
            }
#pragma unroll
            for (int j = 0; j < 9; j++) {
                ull ff[NPN];
#pragma unroll
                for (int t = 0; t < NPN; t++)
                    ff[t] = bcast2((idx[t][j] >= 0) ? __ldg(&feat[idx[t][j]])
                                                    : 0.f);
                const ull* wrow = ws + j * PAIRS;
#pragma unroll
                for (int og = 0; og < PAIRS; og += 2) {
                    ulonglong2 wl =
                        *reinterpret_cast<const ulonglong2*>(wrow + og);
#pragma unroll
                    for (int t = 0; t < NPN; t++) {
                        ffma2(acc2[t][og], ff[t], wl.x);
                        ffma2(acc2[t][og + 1], ff[t], wl.y);
                    }
                }
            }
#pragma unroll
            for (int t = 0; t < NPN; t++) {
                float* orow = out + (size_t)node[t] * ostride;
#pragma unroll
                for (int o = 0; o < COB; o += 4) {
                    float2 p0 = unpack2(acc2[t][o / 2]);
                    float2 p1 = unpack2(acc2[t][o / 2 + 1]);
                    float4 v;
                    v.x = RELU ? fmaxf(p0.x, 0.f) : p0.x;
                    v.y = RELU ? fmaxf(p0.y, 0.f) : p0.y;
                    v.z = RELU ? fmaxf(p1.x, 0.f) : p1.x;
                    v.w = RELU ? fmaxf(p1.y, 0.f) : p1.y;
                    *reinterpret_cast<float4*>(orow + o) = v;
                }
            }
        } else {
            // CIN-split path: S lanes per node, lane s owns groups g*S+s
            constexpr int G = CIN / (4 * S);   // float4 groups per lane
            const int s = tid & (S - 1);
            const int node = blockIdx.x * (256 / S) + (tid / S);

            int idx[9];
#pragma unroll
            for (int j = 0; j < 9; j++) idx[j] = neigh[(size_t)node * 9 + j];
            if (INDIRECT) {
#pragma unroll
                for (int j = 0; j < 9; j++) {
                    if (idx[j] >= 0) {
                        int p = pidx[idx[j]];
                        idx[j] = p < Nfeat ? p : Nfeat - 1;
                    }
                }
            }

            ull acc2[PAIRS];
#pragma unroll
            for (int o2 = 0; o2 < PAIRS; o2++) acc2[o2] = 0;

            for (int j = 0; j < 9; j++) {
                const int id = idx[j];
                float4 f[G];
#pragma unroll
                for (int g = 0; g < G; g++) {
                    if (id >= 0)
                        f[g] = *reinterpret_cast<const float4*>(
                            &feat[(size_t)id * CIN + 4 * (g * S + s)]);
                    else
                        f[g] = make_float4(0.f, 0.f, 0.f, 0.f);
                }
#pragma unroll
                for (int g = 0; g < G; g++) {
                    const int cbase = 4 * (g * S + s);
#pragma unroll
                    for (int cc = 0; cc < 4; cc++) {
                        float fv = cc == 0 ? f[g].x : cc == 1 ? f[g].y
                                 : cc == 2 ? f[g].z : f[g].w;
                        ull ff = bcast2(fv);
                        const ull* wrow = ws + (j * CIN + cbase + cc) * PAIRS;
#pragma unroll
                        for (int og = 0; og < PAIRS; og += 2) {
                            ulonglong2 wl =
                                *reinterpret_cast<const ulonglong2*>(wrow + og);
                            ffma2(acc2[og], ff, wl.x);
                            ffma2(acc2[og + 1], ff, wl.y);
                        }
                    }
                }
            }

            // butterfly reduce across the S lanes of this node
#pragma unroll
            for (int m = S / 2; m >= 1; m >>= 1) {
#pragma unroll
                for (int o2 = 0; o2 < PAIRS; o2++)
                    acc2[o2] = add2(acc2[o2],
                                    __shfl_xor_sync(0xffffffffu, acc2[o2], m));
            }

            // lane s writes float4 chunks o4 = s, s+S, ... (coalesced)
            float* orow = out + (size_t)node * ostride;
#pragma unroll
            for (int o4 = s; o4 < COB / 4; o4 += S) {
                int o = 4 * o4;
                float2 p0 = unpack2(acc2[o / 2]);
                float2 p1 = unpack2(acc2[o / 2 + 1]);
                float4 v;
                v.x = p0.x + b[o + 0];
                v.y = p0.y + b[o + 1];
                v.z = p1.x + b[o + 2];
                v.w = p1.y + b[o + 3];
                if (RELU) {
                    v.x = fmaxf(v.x, 0.f); v.y = fmaxf(v.y, 0.f);
                    v.z = fmaxf(v.z, 0.f); v.w = fmaxf(v.w, 0.f);
                }
                *reinterpret_cast<float4*>(orow + o) = v;
            }
        }
    }
}

// ---------------- launch ------------------------------------------------------
static inline int cdiv(int a, int b) { return (a + b - 1) / b; }

extern "C" void kernel_launch(void* const* d_in, const int* in_sizes, int n_in,
                              void* d_out, int out_size) {
    const float* features = (const float*)d_in[0];
    const int* keys3   = (const int*)d_in[1];
    const int* keys2   = (const int*)d_in[2];
    const int* keys1   = (const int*)d_in[3];
    const int* neighs3 = (const int*)d_in[4];
    const int* neighs2 = (const int*)d_in[5];
    const int* neighs1 = (const int*)d_in[6];
    const float* w_enc1 = (const float*)d_in[7];
    const float* b_enc1 = (const float*)d_in[8];
    const float* w_enc2 = (const float*)d_in[9];
    const float* b_enc2 = (const float*)d_in[10];
    const float* w_enc3 = (const float*)d_in[11];
    const float* b_enc3 = (const float*)d_in[12];
    const float* w_dec1 = (const float*)d_in[13];
    const float* b_dec1 = (const float*)d_in[14];
    const float* w_dec2 = (const float*)d_in[15];
    const float* b_dec2 = (const float*)d_in[16];
    const float* w_head = (const float*)d_in[17];
    const float* b_head = (const float*)d_in[18];
    float* out = (float*)d_out;

    float *x8, *x7p, *x7, *x6p, *x6, *x7dec, *x8dec;
    int *pidx3, *pidx2;
    cudaGetSymbolAddress((void**)&x8, g_x8);
    cudaGetSymbolAddress((void**)&x7p, g_x7p);
    cudaGetSymbolAddress((void**)&x7, g_x7);
    cudaGetSymbolAddress((void**)&x6p, g_x6p);
    cudaGetSymbolAddress((void**)&x6, g_x6);
    cudaGetSymbolAddress((void**)&x7dec, g_x7dec);
    cudaGetSymbolAddress((void**)&x8dec, g_x8dec);
    cudaGetSymbolAddress((void**)&pidx3, g_pidx3);
    cudaGetSymbolAddress((void**)&pidx2, g_pidx2);

    // >48KB dynamic smem instantiations
    cudaFuncSetAttribute((const void*)conv_kernel<32, 64, 4, 1, true, false>,
                         cudaFuncAttributeMaxDynamicSharedMemorySize, 73728);
    cudaFuncSetAttribute((const void*)conv_kernel<64, 32, 4, 1, true, true>,
                         cudaFuncAttributeMaxDynamicSharedMemorySize, 73728);

    // 0: fused prep (pidx3, pidx2, zero pool accumulators)
    prep_kernel<<<2048, 256>>>(keys3, keys2, keys1, pidx3, pidx2, x7p, x6p);

    // 1: enc1 [N3,1]->[N3,16]  packed, NPN=2   (512 CTAs, 576B smem)
    conv_kernel<1, 16, 1, 2, true, false><<<512, 256, 576>>>(
        features, neighs3, nullptr, N3, 16, w_enc1, b_enc1, x8);
    // 2: pool 3->2
    pool_kernel<16><<<cdiv(N3 * 16, 256), 256>>>(x8, pidx3, N3, N2, x7p);
    // 3: enc2 [N2,16]->[N2,32]  S=2  (512 CTAs, 18KB)
    conv_kernel<16, 32, 2, 1, true, false><<<512, 256, 18432>>>(
        x7p, neighs2, nullptr, N2, 32, w_enc2, b_enc2, x7);
    // 4: pool 2->1
    pool_kernel<32><<<cdiv(N2 * 32, 256), 256>>>(x7, pidx2, N2, N1, x6p);
    // 5: enc3 [N1,32]->[N1,64]  S=4  (256 CTAs, 72KB)
    conv_kernel<32, 64, 4, 1, true, false><<<256, 256, 73728>>>(
        x6p, neighs1, nullptr, N1, 64, w_enc3, b_enc3, x6);
    // 6: dec1 (unpool 1->2 fused) [N2,9*64]->[N2,32]  S=4  (1024 CTAs, 72KB)
    conv_kernel<64, 32, 4, 1, true, true><<<1024, 256, 73728>>>(
        x6, neighs2, pidx2, N1, 32, w_dec1, b_dec1, x7dec);
    // 7: dec2 (unpool 2->3 fused) [N3,9*32]->[N3,16]  S=2  (2048 CTAs, 18KB)
    conv_kernel<32, 16, 2, 1, true, true><<<2048, 256, 18432>>>(
        x7dec, neighs3, pidx3, N2, 16, w_dec2, b_dec2, x8dec);
    // 8: head [N3,16]->[N3,1], no relu  (512 CTAs, 576B)
    conv_kernel<16, 1, 1, 2, false, false><<<512, 256, 576>>>(
        x8dec, neighs3, nullptr, N3, 1, w_head, b_head, out);
}

// round 12
// speedup vs baseline: 3.9577x; 3.9577x over previous
#include <cuda_runtime.h>

#define N3 262144
#define N2 65536
#define N1 16384

typedef unsigned long long ull;

// ---------------- scratch (device globals; no allocations allowed) ----------
__device__ float g_x8   [N3 * 16];
__device__ float g_x7p  [N2 * 16];
__device__ float g_x7   [N2 * 32];
__device__ float g_x6p  [N1 * 32];
__device__ float g_x6   [N1 * 64];
__device__ float g_x7dec[N2 * 32];
__device__ float g_x8dec[N3 * 16];
__device__ int   g_pidx3[N3];
__device__ int   g_pidx2[N2];

// ---------------- packed f32x2 helpers ---------------------------------------
__device__ __forceinline__ ull pack2(float lo, float hi) {
    ull r;
    asm("mov.b64 %0, {%1, %2};" : "=l"(r) : "f"(lo), "f"(hi));
    return r;
}
__device__ __forceinline__ ull bcast2(float v) {
    ull r;
    asm("mov.b64 %0, {%1, %1};" : "=l"(r) : "f"(v));
    return r;
}
__device__ __forceinline__ void ffma2(ull& d, ull a, ull b) {
    asm("fma.rn.f32x2 %0, %1, %2, %0;" : "+l"(d) : "l"(a), "l"(b));
}
__device__ __forceinline__ float2 unpack2(ull v) {
    float2 r;
    asm("mov.b64 {%0, %1}, %2;" : "=f"(r.x), "=f"(r.y) : "l"(v));
    return r;
}

// ---------------- fused prep: pidx3, pidx2, zero x7p, zero x6p ---------------
__device__ __forceinline__ int lower_bound_shift(const int* __restrict__ keys,
                                                 int Np, int v) {
    int lo = 0, hi = Np;
    while (lo < hi) {
        int mid = (lo + hi) >> 1;
        if (keys[mid] < v) lo = mid + 1; else hi = mid;
    }
    return lo;
}

__global__ void prep_kernel(const int* __restrict__ keys3,
                            const int* __restrict__ keys2,
                            const int* __restrict__ keys1,
                            int* __restrict__ pidx3, int* __restrict__ pidx2,
                            float* __restrict__ x7p, float* __restrict__ x6p) {
    const int T0 = N3;
    const int T1 = T0 + N2;
    const int T2 = T1 + N2 * 16;
    const int T3 = T2 + N1 * 32;
    int i = blockIdx.x * blockDim.x + threadIdx.x;
    int stride = gridDim.x * blockDim.x;
    for (; i < T3; i += stride) {
        if (i < T0) {
            pidx3[i] = lower_bound_shift(keys2, N2, keys3[i] >> 2);
        } else if (i < T1) {
            int k = i - T0;
            pidx2[k] = lower_bound_shift(keys1, N1, keys2[k] >> 2);
        } else if (i < T2) {
            x7p[i - T1] = 0.0f;
        } else {
            x6p[i - T2] = 0.0f;
        }
    }
}

// segment-max pool. Post-ReLU values >= 0, so int-bit atomicMax == float max
// and 0-init matches the reference's (-inf -> 0) fill.
template <int C>
__global__ void pool_kernel(const float* __restrict__ child,
                            const int* __restrict__ pidx,
                            int Nc, int Np, float* __restrict__ parent) {
    int i = blockIdx.x * blockDim.x + threadIdx.x;
    if (i >= Nc * C) return;
    int node = i / C;
    int c = i - node * C;
    int p = pidx[node];
    if (p < Np) {
        float v = child[i];
        atomicMax(reinterpret_cast<int*>(&parent[(size_t)p * C + c]),
                  __float_as_int(v));
    }
}

// ---------------- fused gather + (9*CIN -> COB) conv, packed f32x2 -----------
// Per-j structure: hoist ALL gather loads of a chunk (KC float4 x NPN, MLP=8)
// BEFORE the FMA block -> L2 gather latency hidden by in-thread ILP.
// Weight pairs staged once in shared, read with warp-UNIFORM LDS.128 (2 pairs
// per load -> 2*NPN ffma2 per LDS). INDIRECT fuses the unpool gather.
template <int CIN, int COB, int NPN, bool RELU, bool INDIRECT>
__global__ void __launch_bounds__(128)
conv_kernel(const float* __restrict__ feat, const int* __restrict__ neigh,
            const int* __restrict__ pidx, int Nfeat, int ostride,
            const float* __restrict__ w, const float* __restrict__ b,
            float* __restrict__ out) {
    extern __shared__ __align__(16) char smem_raw[];
    const int tid = threadIdx.x;
    const int oc_base = blockIdx.y * COB;
    const int cin9 = 9 * CIN;

    int node[NPN];
    int idx[NPN][9];
#pragma unroll
    for (int t = 0; t < NPN; t++) {
        node[t] = blockIdx.x * (128 * NPN) + t * 128 + tid;
#pragma unroll
        for (int j = 0; j < 9; j++) idx[t][j] = neigh[(size_t)node[t] * 9 + j];
        if (INDIRECT) {
#pragma unroll
            for (int j = 0; j < 9; j++) {
                if (idx[t][j] >= 0) {
                    int p = pidx[idx[t][j]];
                    idx[t][j] = p < Nfeat ? p : Nfeat - 1;
                }
            }
        }
    }

    if constexpr (COB == 1) {
        // head layer: scalar acc, hoisted gather loads per j
        float* ws = reinterpret_cast<float*>(smem_raw);
        for (int s = tid; s < cin9; s += 128) ws[s] = w[s];
        __syncthreads();

        float acc[NPN];
#pragma unroll
        for (int t = 0; t < NPN; t++) acc[t] = b[0];
        for (int j = 0; j < 9; j++) {
            float4 f[NPN][CIN / 4];
#pragma unroll
            for (int t = 0; t < NPN; t++)
#pragma unroll
                for (int k = 0; k < CIN / 4; k++)
                    f[t][k] = (idx[t][j] >= 0)
                        ? *reinterpret_cast<const float4*>(
                              &feat[(size_t)idx[t][j] * CIN + 4 * k])
                        : make_float4(0.f, 0.f, 0.f, 0.f);
#pragma unroll
            for (int k = 0; k < CIN / 4; k++) {
                float4 wv = *reinterpret_cast<const float4*>(
                    &ws[j * CIN + 4 * k]);
#pragma unroll
                for (int t = 0; t < NPN; t++)
                    acc[t] += f[t][k].x * wv.x + f[t][k].y * wv.y +
                              f[t][k].z * wv.z + f[t][k].w * wv.w;
            }
        }
#pragma unroll
        for (int t = 0; t < NPN; t++)
            out[(size_t)node[t] * ostride] = RELU ? fmaxf(acc[t], 0.f) : acc[t];
    } else {
        constexpr int PAIRS = COB / 2;
        ull* ws = reinterpret_cast<ull*>(smem_raw);
        // ws[rc * PAIRS + o2] = pack(w[oc+2o2][rc], w[oc+2o2+1][rc])
        for (int s = tid; s < cin9 * PAIRS; s += 128) {
            int rc = s / PAIRS;
            int o2 = s - rc * PAIRS;
            ws[s] = pack2(w[(size_t)(oc_base + 2 * o2) * cin9 + rc],
                          w[(size_t)(oc_base + 2 * o2 + 1) * cin9 + rc]);
        }
        __syncthreads();

        ull acc2[NPN][PAIRS];
#pragma unroll
        for (int o2 = 0; o2 < PAIRS; o2++) {
            ull bv = pack2(b[oc_base + 2 * o2], b[oc_base + 2 * o2 + 1]);
#pragma unroll
            for (int t = 0; t < NPN; t++) acc2[t][o2] = bv;
        }

        if constexpr (CIN == 1) {
            // enc1: hoist all 9 scalar gathers up front
            float fv[NPN][9];
#pragma unroll
            for (int t = 0; t < NPN; t++)
#pragma unroll
                for (int j = 0; j < 9; j++)
                    fv[t][j] = (idx[t][j] >= 0) ? __ldg(&feat[idx[t][j]]) : 0.f;
#pragma unroll
            for (int j = 0; j < 9; j++) {
                ull ff[NPN];
#pragma unroll
                for (int t = 0; t < NPN; t++) ff[t] = bcast2(fv[t][j]);
                const ull* wrow = ws + j * PAIRS;
#pragma unroll
                for (int og = 0; og < PAIRS; og += 2) {
                    ulonglong2 wl =
                        *reinterpret_cast<const ulonglong2*>(wrow + og);
#pragma unroll
                    for (int t = 0; t < NPN; t++) {
                        ffma2(acc2[t][og], ff[t], wl.x);
                        ffma2(acc2[t][og + 1], ff[t], wl.y);
                    }
                }
            }
        } else {
            constexpr int CIN4 = CIN / 4;
            // chunk size: <=8 live float4 per thread, MLP = KC*NPN >= 8
            constexpr int KC = (CIN4 * NPN <= 8) ? CIN4 : (8 / NPN);
            for (int j = 0; j < 9; j++) {
#pragma unroll
                for (int k0 = 0; k0 < CIN4; k0 += KC) {
                    float4 f[NPN][KC];
                    // --- hoisted load phase (all KC*NPN gathers in flight) ---
#pragma unroll
                    for (int t = 0; t < NPN; t++) {
                        const int id = idx[t][j];
#pragma unroll
                        for (int k = 0; k < KC; k++)
                            f[t][k] = (id >= 0)
                                ? *reinterpret_cast<const float4*>(
                                      &feat[(size_t)id * CIN + 4 * (k0 + k)])
                                : make_float4(0.f, 0.f, 0.f, 0.f);
                    }
                    // --- FMA phase ---
#pragma unroll
                    for (int k = 0; k < KC; k++) {
#pragma unroll
                        for (int cc = 0; cc < 4; cc++) {
                            ull ff[NPN];
#pragma unroll
                            for (int t = 0; t < NPN; t++) {
                                float v = cc == 0 ? f[t][k].x
                                        : cc == 1 ? f[t][k].y
                                        : cc == 2 ? f[t][k].z : f[t][k].w;
                                ff[t] = bcast2(v);
                            }
                            const ull* wrow =
                                ws + (j * CIN + 4 * (k0 + k) + cc) * PAIRS;
#pragma unroll
                            for (int og = 0; og < PAIRS; og += 2) {
                                ulonglong2 wl =
                                    *reinterpret_cast<const ulonglong2*>(
                                        wrow + og);
#pragma unroll
                                for (int t = 0; t < NPN; t++) {
                                    ffma2(acc2[t][og], ff[t], wl.x);
                                    ffma2(acc2[t][og + 1], ff[t], wl.y);
                                }
                            }
                        }
                    }
                }
            }
        }

#pragma unroll
        for (int t = 0; t < NPN; t++) {
            float* orow = out + (size_t)node[t] * ostride + oc_base;
#pragma unroll
            for (int o = 0; o < COB; o += 4) {
                float2 p0 = unpack2(acc2[t][o / 2]);
                float2 p1 = unpack2(acc2[t][o / 2 + 1]);
                float4 v;
                v.x = RELU ? fmaxf(p0.x, 0.f) : p0.x;
                v.y = RELU ? fmaxf(p0.y, 0.f) : p0.y;
                v.z = RELU ? fmaxf(p1.x, 0.f) : p1.x;
                v.w = RELU ? fmaxf(p1.y, 0.f) : p1.y;
                *reinterpret_cast<float4*>(orow + o) = v;
            }
        }
    }
}

// ---------------- launch ------------------------------------------------------
static inline int cdiv(int a, int b) { return (a + b - 1) / b; }

extern "C" void kernel_launch(void* const* d_in, const int* in_sizes, int n_in,
                              void* d_out, int out_size) {
    const float* features = (const float*)d_in[0];
    const int* keys3   = (const int*)d_in[1];
    const int* keys2   = (const int*)d_in[2];
    const int* keys1   = (const int*)d_in[3];
    const int* neighs3 = (const int*)d_in[4];
    const int* neighs2 = (const int*)d_in[5];
    const int* neighs1 = (const int*)d_in[6];
    const float* w_enc1 = (const float*)d_in[7];
    const float* b_enc1 = (const float*)d_in[8];
    const float* w_enc2 = (const float*)d_in[9];
    const float* b_enc2 = (const float*)d_in[10];
    const float* w_enc3 = (const float*)d_in[11];
    const float* b_enc3 = (const float*)d_in[12];
    const float* w_dec1 = (const float*)d_in[13];
    const float* b_dec1 = (const float*)d_in[14];
    const float* w_dec2 = (const float*)d_in[15];
    const float* b_dec2 = (const float*)d_in[16];
    const float* w_head = (const float*)d_in[17];
    const float* b_head = (const float*)d_in[18];
    float* out = (float*)d_out;

    float *x8, *x7p, *x7, *x6p, *x6, *x7dec, *x8dec;
    int *pidx3, *pidx2;
    cudaGetSymbolAddress((void**)&x8, g_x8);
    cudaGetSymbolAddress((void**)&x7p, g_x7p);
    cudaGetSymbolAddress((void**)&x7, g_x7);
    cudaGetSymbolAddress((void**)&x6p, g_x6p);
    cudaGetSymbolAddress((void**)&x6, g_x6);
    cudaGetSymbolAddress((void**)&x7dec, g_x7dec);
    cudaGetSymbolAddress((void**)&x8dec, g_x8dec);
    cudaGetSymbolAddress((void**)&pidx3, g_pidx3);
    cudaGetSymbolAddress((void**)&pidx2, g_pidx2);

    // dec1 needs 72KB dynamic smem
    cudaFuncSetAttribute((const void*)conv_kernel<64, 32, 1, true, true>,
                         cudaFuncAttributeMaxDynamicSharedMemorySize, 73728);

    // 0: fused prep (pidx3, pidx2, zero pool accumulators)
    prep_kernel<<<2048, 256>>>(keys3, keys2, keys1, pidx3, pidx2, x7p, x6p);

    // 1: enc1 [N3,1]->[N3,16]  NPN=2  (1024 CTAs, 576B)
    conv_kernel<1, 16, 2, true, false><<<dim3(N3 / 256, 1), 128, 576>>>(
        features, neighs3, nullptr, N3, 16, w_enc1, b_enc1, x8);
    // 2: pool 3->2
    pool_kernel<16><<<cdiv(N3 * 16, 256), 256>>>(x8, pidx3, N3, N2, x7p);
    // 3: enc2 [N2,16]->[N2,32]  NPN=2, full COUT  (256 CTAs, 18KB)
    conv_kernel<16, 32, 2, true, false><<<dim3(N2 / 256, 1), 128, 18432>>>(
        x7p, neighs2, nullptr, N2, 32, w_enc2, b_enc2, x7);
    // 4: pool 2->1
    pool_kernel<32><<<cdiv(N2 * 32, 256), 256>>>(x7, pidx2, N2, N1, x6p);
    // 5: enc3 [N1,32]->[N1,64]  COB=16 x y4 for warp count  (512 CTAs, 18KB)
    conv_kernel<32, 16, 1, true, false><<<dim3(N1 / 128, 4), 128, 18432>>>(
        x6p, neighs1, nullptr, N1, 64, w_enc3, b_enc3, x6);
    // 6: dec1 (unpool 1->2 fused) [N2,9*64]->[N2,32]  (512 CTAs, 72KB)
    conv_kernel<64, 32, 1, true, true><<<dim3(N2 / 128, 1), 128, 73728>>>(
        x6, neighs2, pidx2, N1, 32, w_dec1, b_dec1, x7dec);
    // 7: dec2 (unpool 2->3 fused) [N3,9*32]->[N3,16]  NPN=2  (1024 CTAs, 18KB)
    conv_kernel<32, 16, 2, true, true><<<dim3(N3 / 256, 1), 128, 18432>>>(
        x7dec, neighs3, pidx3, N2, 16, w_dec2, b_dec2, x8dec);
    // 8: head [N3,16]->[N3,1]  NPN=2, no relu  (1024 CTAs, 576B)
    conv_kernel<16, 1, 2, false, false><<<dim3(N3 / 256, 1), 128, 576>>>(
        x8dec, neighs3, nullptr, N3, 1, w_head, b_head, out);
}